// round 9
// baseline (speedup 1.0000x reference)
#include <cuda_runtime.h>
#include <cstdint>

#define N_NODES 100000
#define N_EDGES 1250000
#define D_IN    64
#define OUT_COLS 300
#define WC_COLS 320     // padded output columns
#define WC_ROWS 192     // 3 x 64 (T0, T1, T2p)
#define SCAN_BS 1024
#define SCAN_NB ((N_NODES + SCAN_BS - 1) / SCAN_BS)   // 98

// ---------------- scratch (device globals: allocation-free) ----------------
__device__ __align__(16) float  g_dis[N_NODES];          // deg, then rsqrt(deg)
__device__ __align__(16) int    g_cnt[N_NODES];          // in-degree histogram
__device__ __align__(16) int    g_scan[N_NODES];         // block-inclusive scan
__device__ __align__(16) int    g_bsum[SCAN_NB];         // per-block sums
__device__ __align__(16) int    g_boff[SCAN_NB];         // exclusive block offsets
__device__ __align__(16) int    g_off[N_NODES + 1];      // CSR offsets
__device__ __align__(16) int    g_cur[N_NODES];          // fill cursors
__device__ __align__(16) float2 g_pack[N_EDGES];         // (src bitcast, w_hat)
__device__ __align__(16) float  g_T1[N_NODES * D_IN];    // prop(x)
__device__ __align__(16) float  g_T2[N_NODES * D_IN];    // prop(T1)
__device__ __align__(16) float  g_Wc[WC_ROWS * WC_COLS]; // combined weight matrix
__device__ __align__(16) float  g_bias[WC_COLS];         // concat bias (padded)
__device__ int g_is64;                                   // edge_index dtype flag

// ---------------- edge index access (dtype-adaptive) ----------------
__global__ void detect_dtype_kernel(const int* __restrict__ ei32) {
    __shared__ int nz;
    if (threadIdx.x == 0) nz = 0;
    __syncthreads();
    int w = 2 * threadIdx.x + 1;   // odd words of first 512 ints
    if (ei32[w] != 0) atomicAdd(&nz, 1);
    __syncthreads();
    if (threadIdx.x == 0) g_is64 = (nz == 0) ? 1 : 0;
}

__device__ __forceinline__ void load_edge(const void* ei, int e, unsigned& r, unsigned& c) {
    if (g_is64) {
        const long long* p = (const long long*)ei;
        r = (unsigned)(int)p[e];
        c = (unsigned)(int)p[N_EDGES + e];
    } else {
        const int* p = (const int*)ei;
        r = (unsigned)p[e];
        c = (unsigned)p[N_EDGES + e];
    }
}

// ---------------- kernels ----------------

__global__ void zero_kernel() {
    int i = blockIdx.x * blockDim.x + threadIdx.x;
    if (i < N_NODES) { g_dis[i] = 0.f; g_cnt[i] = 0; }
}

__global__ void deg_hist_kernel(const void* __restrict__ ei, const float* __restrict__ ew) {
    int e = blockIdx.x * blockDim.x + threadIdx.x;
    if (e < N_EDGES) {
        unsigned r, c;
        load_edge(ei, e, r, c);
        if (r < N_NODES) atomicAdd(&g_dis[r], ew[e]);
        if (c < N_NODES) atomicAdd(&g_cnt[c], 1);
    }
}

__global__ void dis_kernel() {
    int i = blockIdx.x * blockDim.x + threadIdx.x;
    if (i < N_NODES) {
        float d = g_dis[i];
        g_dis[i] = (d > 0.f) ? rsqrtf(d) : 0.f;
    }
}

// ---- 3-kernel exclusive scan of g_cnt -> g_off ----
__global__ void scan1_kernel() {
    __shared__ int s[SCAN_BS];
    int t = threadIdx.x;
    int i = blockIdx.x * SCAN_BS + t;
    int v = (i < N_NODES) ? g_cnt[i] : 0;
    s[t] = v;
    __syncthreads();
    for (int d = 1; d < SCAN_BS; d <<= 1) {
        int add = (t >= d) ? s[t - d] : 0;
        __syncthreads();
        s[t] += add;
        __syncthreads();
    }
    if (i < N_NODES) g_scan[i] = s[t];
    if (t == SCAN_BS - 1) g_bsum[blockIdx.x] = s[t];
}

__global__ void scan2_kernel() {
    __shared__ int s[128];
    int t = threadIdx.x;
    int v = (t < SCAN_NB) ? g_bsum[t] : 0;
    s[t] = v;
    __syncthreads();
    for (int d = 1; d < 128; d <<= 1) {
        int add = (t >= d) ? s[t - d] : 0;
        __syncthreads();
        s[t] += add;
        __syncthreads();
    }
    if (t < SCAN_NB) g_boff[t] = s[t] - v;   // exclusive
}

__global__ void finalize_off_kernel() {
    int i = blockIdx.x * blockDim.x + threadIdx.x;
    if (i < N_NODES) {
        int incl = g_scan[i] + g_boff[i / SCAN_BS];
        int excl = incl - g_cnt[i];
        g_off[i] = excl;
        g_cur[i] = excl;
        if (i == N_NODES - 1) g_off[N_NODES] = incl;
    }
}

__global__ void fill_kernel(const void* __restrict__ ei, const float* __restrict__ ew) {
    int e = blockIdx.x * blockDim.x + threadIdx.x;
    if (e < N_EDGES) {
        unsigned r, c;
        load_edge(ei, e, r, c);
        if (r >= N_NODES || c >= N_NODES) return;
        float w = -g_dis[r] * ew[e] * g_dis[c];
        unsigned slot = (unsigned)atomicAdd(&g_cur[c], 1);
        if (slot >= N_EDGES) slot = N_EDGES - 1;
        g_pack[slot] = make_float2(__int_as_float((int)r), w);
    }
}

// gather prop: one warp per node, lane owns a float2 of the 64-dim feature
__global__ void __launch_bounds__(256)
prop_kernel(const float* __restrict__ x, int phase) {
    int gt = blockIdx.x * blockDim.x + threadIdx.x;
    int node = gt >> 5;
    int lane = gt & 31;
    if (node >= N_NODES) return;
    const float* src = (phase == 0) ? x : g_T1;
    float*       dst = (phase == 0) ? g_T1 : g_T2;
    int beg = g_off[node];
    int end = g_off[node + 1];
    if (beg < 0) beg = 0;
    if (end > N_EDGES) end = N_EDGES;
    const float2* s2 = reinterpret_cast<const float2*>(src);
    float ax = 0.f, ay = 0.f;
    int j = beg;
    for (; j + 2 <= end; j += 2) {
        float2 p0 = g_pack[j];
        float2 p1 = g_pack[j + 1];
        unsigned r0 = min((unsigned)__float_as_int(p0.x), N_NODES - 1u);
        unsigned r1 = min((unsigned)__float_as_int(p1.x), N_NODES - 1u);
        float2 v0 = s2[r0 * 32 + lane];
        float2 v1 = s2[r1 * 32 + lane];
        ax += p0.y * v0.x;  ay += p0.y * v0.y;
        ax += p1.y * v1.x;  ay += p1.y * v1.y;
    }
    if (j < end) {
        float2 p0 = g_pack[j];
        unsigned r0 = min((unsigned)__float_as_int(p0.x), N_NODES - 1u);
        float2 v0 = s2[r0 * 32 + lane];
        ax += p0.y * v0.x;  ay += p0.y * v0.y;
    }
    reinterpret_cast<float2*>(dst)[node * 32 + lane] = make_float2(ax, ay);
}

// Build combined weight matrix Wc[192][320] and bias[320]
__global__ void prep_weights_kernel(
    const float* __restrict__ W10, const float* __restrict__ b1,
    const float* __restrict__ W20, const float* __restrict__ W21, const float* __restrict__ b2,
    const float* __restrict__ W30, const float* __restrict__ W31, const float* __restrict__ W32,
    const float* __restrict__ b3)
{
    int i = blockIdx.x * blockDim.x + threadIdx.x;
    if (i >= WC_ROWS * WC_COLS) return;
    int k = i / WC_COLS;
    int c = i % WC_COLS;
    float v = 0.f;
    if (k < 64) {
        if (c < 100)       v = W10[k * 100 + c];
        else if (c < 200)  v = W20[k * 100 + (c - 100)];
        else if (c < 300)  v = W30[k * 100 + (c - 200)] - W32[k * 100 + (c - 200)];
    } else if (k < 128) {
        int kk = k - 64;
        if (c >= 100 && c < 200)      v = W21[kk * 100 + (c - 100)];
        else if (c >= 200 && c < 300) v = W31[kk * 100 + (c - 200)];
    } else {
        int kk = k - 128;
        if (c >= 200 && c < 300) v = 2.f * W32[kk * 100 + (c - 200)];
    }
    g_Wc[i] = v;
    if (i < WC_COLS) {
        float bv = 0.f;
        if (i < 100)      bv = b1[i];
        else if (i < 200) bv = b2[i - 100];
        else if (i < 300) bv = b3[i - 200];
        g_bias[i] = bv;
    }
}

// GEMM: out[100000, 300] = [x | T1 | T2p] @ Wc + bias
// Block: 256 nodes x 64 cols, 256 threads. Thread: 8 nodes x 8 cols via
// packed fma.rn.f32x2 (FFMA2 = 2x scalar FFMA rate on sm_103a).
// grid.y = column tile (5 tiles of 64); K chunks per tile: {1,2,2,3,3}.
#define U_STRIDE 72   // 64+8: divisible by 4 (16B-aligned f4 slots); banks 8 apart for u reads
#define W_STRIDE 68   // 64+4: divisible by 4 -> every float4 store 16B aligned (was 66: TRAP)

__global__ void __launch_bounds__(256, 2)
gemm_kernel(const float* __restrict__ x, float* __restrict__ out)
{
    extern __shared__ float sm[];
    float* Usm = sm;                    // [256][U_STRIDE]
    float* Wsm = sm + 256 * U_STRIDE;   // [64][W_STRIDE]

    const int tid = threadIdx.x;
    const int tx = tid & 7;    // 8 col-groups of 8 cols
    const int ty = tid >> 3;   // 0..31 ; this thread's nodes: ty + 32*j
    const int nodeBase = blockIdx.x * 256;
    const int ct = blockIdx.y;
    const int colBase = ct * 64;
    const int nchunks = (ct == 0) ? 1 : (ct < 3) ? 2 : 3;

    unsigned long long acc[8][4];
#pragma unroll
    for (int j = 0; j < 8; j++)
#pragma unroll
        for (int c = 0; c < 4; c++) acc[j][c] = 0ull;

    for (int kc = 0; kc < nchunks; kc++) {
        const float4* src = (kc == 0) ? reinterpret_cast<const float4*>(x)
                          : (kc == 1) ? reinterpret_cast<const float4*>(g_T1)
                                      : reinterpret_cast<const float4*>(g_T2);
        // U load: 256 nodes x 16 float4 = 4096 slots -> 16 per thread
#pragma unroll
        for (int i = 0; i < 16; i++) {
            int idx = tid + i * 256;
            int node = idx >> 4;
            int k4 = idx & 15;
            int gn = nodeBase + node;
            float4 v = make_float4(0.f, 0.f, 0.f, 0.f);
            if (gn < N_NODES) v = src[gn * 16 + k4];
            *reinterpret_cast<float4*>(&Usm[node * U_STRIDE + k4 * 4]) = v;
        }
        // W load: 64 k x 16 float4 = 1024 slots -> 4 per thread
#pragma unroll
        for (int i = 0; i < 4; i++) {
            int idx = tid + i * 256;
            int k = idx >> 4;
            int c4 = idx & 15;
            float4 wv = *reinterpret_cast<const float4*>(
                &g_Wc[(kc * 64 + k) * WC_COLS + colBase + c4 * 4]);
            *reinterpret_cast<float4*>(&Wsm[k * W_STRIDE + c4 * 4]) = wv;
        }
        __syncthreads();

        const float* up = Usm + ty * U_STRIDE;
        const float* wp = Wsm + tx * 8;
#pragma unroll 8
        for (int k = 0; k < 64; k++) {
            const float* wr = wp + k * W_STRIDE;
            unsigned long long w2[4];
#pragma unroll
            for (int c = 0; c < 4; c++)
                w2[c] = *reinterpret_cast<const unsigned long long*>(&wr[c * 2]);
#pragma unroll
            for (int j = 0; j < 8; j++) {
                float u = up[j * (32 * U_STRIDE) + k];
                unsigned long long u2;
                asm("mov.b64 %0, {%1, %1};" : "=l"(u2) : "f"(u));
#pragma unroll
                for (int c = 0; c < 4; c++)
                    asm("fma.rn.f32x2 %0, %1, %2, %0;" : "+l"(acc[j][c]) : "l"(u2), "l"(w2[c]));
            }
        }
        __syncthreads();
    }

    // epilogue: add bias, store float2 pairs (all 8B aligned: col even, row stride 1200B)
#pragma unroll
    for (int j = 0; j < 8; j++) {
        int node = nodeBase + ty + 32 * j;
        if (node >= N_NODES) continue;
        float* orow = out + (long long)node * OUT_COLS;
#pragma unroll
        for (int c = 0; c < 4; c++) {
            int col = colBase + tx * 8 + c * 2;
            if (col < OUT_COLS) {
                float lo, hi;
                asm("mov.b64 {%0, %1}, %2;" : "=f"(lo), "=f"(hi) : "l"(acc[j][c]));
                lo += g_bias[col];
                hi += g_bias[col + 1];
                *reinterpret_cast<float2*>(&orow[col]) = make_float2(lo, hi);
            }
        }
    }
}

// ---------------- launch ----------------
extern "C" void kernel_launch(void* const* d_in, const int* in_sizes, int n_in,
                              void* d_out, int out_size)
{
    // Resolve inputs BY SIZE SIGNATURE:
    const float* x = nullptr;
    const void*  ei = nullptr;
    const float* ew = nullptr;
    const float* Ws[6] = {};
    const float* Bs[3] = {};
    int nw = 0, nb = 0;
    for (int i = 0; i < n_in; i++) {
        int s = in_sizes[i];
        if (s == N_NODES * D_IN)      x = (const float*)d_in[i];
        else if (s == 2 * N_EDGES)    ei = d_in[i];
        else if (s == N_EDGES)        ew = (const float*)d_in[i];
        else if (s == D_IN * 100)     { if (nw < 6) Ws[nw++] = (const float*)d_in[i]; }
        else if (s == 100)            { if (nb < 3) Bs[nb++] = (const float*)d_in[i]; }
    }
    if (!x)  x  = (const float*)d_in[0];
    if (!ei) ei = d_in[1];
    if (!ew) ew = (const float*)d_in[2];
    if (nw < 6) {
        Ws[0] = (const float*)d_in[3];  Ws[1] = (const float*)d_in[5];
        Ws[2] = (const float*)d_in[6];  Ws[3] = (const float*)d_in[8];
        Ws[4] = (const float*)d_in[9];  Ws[5] = (const float*)d_in[10];
    }
    if (nb < 3) {
        Bs[0] = (const float*)d_in[4];  Bs[1] = (const float*)d_in[7];
        Bs[2] = (const float*)d_in[11];
    }
    float* out = (float*)d_out;

    // dynamic smem opt-in for the GEMM (non-stream API, capture-legal)
    const int gemm_smem = (256 * U_STRIDE + 64 * W_STRIDE) * sizeof(float);  // 91136 B
    cudaFuncSetAttribute(gemm_kernel, cudaFuncAttributeMaxDynamicSharedMemorySize, gemm_smem);

    const int B = 256;
    const int nodeGrid = (N_NODES + B - 1) / B;
    const int edgeGrid = (N_EDGES + B - 1) / B;

    detect_dtype_kernel<<<1, 256>>>((const int*)ei);
    zero_kernel<<<nodeGrid, B>>>();
    deg_hist_kernel<<<edgeGrid, B>>>(ei, ew);
    dis_kernel<<<nodeGrid, B>>>();
    scan1_kernel<<<SCAN_NB, SCAN_BS>>>();
    scan2_kernel<<<1, 128>>>();
    finalize_off_kernel<<<nodeGrid, B>>>();
    fill_kernel<<<edgeGrid, B>>>(ei, ew);

    {   // T1 = P x ; T2p = P T1
        long long items = (long long)N_NODES * 32;
        int grid = (int)((items + B - 1) / B);
        prop_kernel<<<grid, B>>>(x, 0);
        prop_kernel<<<grid, B>>>(x, 1);
    }

    prep_weights_kernel<<<(WC_ROWS * WC_COLS + B - 1) / B, B>>>(
        Ws[0], Bs[0], Ws[1], Ws[2], Bs[1], Ws[3], Ws[4], Ws[5], Bs[2]);

    {
        dim3 grid((N_NODES + 255) / 256, 5);
        gemm_kernel<<<grid, 256, gemm_smem>>>(x, out);
    }
}

// round 11
// speedup vs baseline: 1.5028x; 1.5028x over previous
#include <cuda_runtime.h>
#include <cuda_bf16.h>
#include <cstdint>

#define N_NODES 100000
#define N_EDGES 1250000
#define D_IN    64
#define OUT_COLS 300
#define WC_COLS 320
#define WC_ROWS 192
#define SCAN_BS 1024
#define SCAN_NB ((N_NODES + SCAN_BS - 1) / SCAN_BS)   // 98

// ---------------- scratch (device globals) ----------------
__device__ __align__(16) float  g_dis[N_NODES];
__device__ __align__(16) int    g_cnt[N_NODES];
__device__ __align__(16) int    g_scan[N_NODES];
__device__ __align__(16) int    g_bsum[SCAN_NB];
__device__ __align__(16) int    g_boff[SCAN_NB];
__device__ __align__(16) int    g_off[N_NODES + 1];
__device__ __align__(16) int    g_cur[N_NODES];
__device__ __align__(16) float2 g_pack[N_EDGES];
__device__ __align__(16) float  g_T1[N_NODES * D_IN];
__device__ __align__(16) float  g_T2[N_NODES * D_IN];
__device__ __align__(16) float  g_WcT[WC_COLS * WC_ROWS];  // [col][k]
__device__ __align__(16) float  g_bias[WC_COLS];
__device__ int g_is64;

// ---------------- edge dtype handling ----------------
__global__ void detect_dtype_kernel(const int* __restrict__ ei32) {
    __shared__ int nz;
    if (threadIdx.x == 0) nz = 0;
    __syncthreads();
    int w = 2 * threadIdx.x + 1;
    if (ei32[w] != 0) atomicAdd(&nz, 1);
    __syncthreads();
    if (threadIdx.x == 0) g_is64 = (nz == 0) ? 1 : 0;
}
__device__ __forceinline__ void load_edge(const void* ei, int e, unsigned& r, unsigned& c) {
    if (g_is64) {
        const long long* p = (const long long*)ei;
        r = (unsigned)(int)p[e];  c = (unsigned)(int)p[N_EDGES + e];
    } else {
        const int* p = (const int*)ei;
        r = (unsigned)p[e];       c = (unsigned)p[N_EDGES + e];
    }
}

// ---------------- graph pipeline (identical to passing R9) ----------------
__global__ void zero_kernel() {
    int i = blockIdx.x * blockDim.x + threadIdx.x;
    if (i < N_NODES) { g_dis[i] = 0.f; g_cnt[i] = 0; }
}
__global__ void deg_hist_kernel(const void* __restrict__ ei, const float* __restrict__ ew) {
    int e = blockIdx.x * blockDim.x + threadIdx.x;
    if (e < N_EDGES) {
        unsigned r, c; load_edge(ei, e, r, c);
        if (r < N_NODES) atomicAdd(&g_dis[r], ew[e]);
        if (c < N_NODES) atomicAdd(&g_cnt[c], 1);
    }
}
__global__ void dis_kernel() {
    int i = blockIdx.x * blockDim.x + threadIdx.x;
    if (i < N_NODES) {
        float d = g_dis[i];
        g_dis[i] = (d > 0.f) ? rsqrtf(d) : 0.f;
    }
}
__global__ void scan1_kernel() {
    __shared__ int s[SCAN_BS];
    int t = threadIdx.x;
    int i = blockIdx.x * SCAN_BS + t;
    int v = (i < N_NODES) ? g_cnt[i] : 0;
    s[t] = v; __syncthreads();
    for (int d = 1; d < SCAN_BS; d <<= 1) {
        int add = (t >= d) ? s[t - d] : 0;
        __syncthreads(); s[t] += add; __syncthreads();
    }
    if (i < N_NODES) g_scan[i] = s[t];
    if (t == SCAN_BS - 1) g_bsum[blockIdx.x] = s[t];
}
__global__ void scan2_kernel() {
    __shared__ int s[128];
    int t = threadIdx.x;
    int v = (t < SCAN_NB) ? g_bsum[t] : 0;
    s[t] = v; __syncthreads();
    for (int d = 1; d < 128; d <<= 1) {
        int add = (t >= d) ? s[t - d] : 0;
        __syncthreads(); s[t] += add; __syncthreads();
    }
    if (t < SCAN_NB) g_boff[t] = s[t] - v;
}
__global__ void finalize_off_kernel() {
    int i = blockIdx.x * blockDim.x + threadIdx.x;
    if (i < N_NODES) {
        int incl = g_scan[i] + g_boff[i / SCAN_BS];
        int excl = incl - g_cnt[i];
        g_off[i] = excl; g_cur[i] = excl;
        if (i == N_NODES - 1) g_off[N_NODES] = incl;
    }
}
__global__ void fill_kernel(const void* __restrict__ ei, const float* __restrict__ ew) {
    int e = blockIdx.x * blockDim.x + threadIdx.x;
    if (e < N_EDGES) {
        unsigned r, c; load_edge(ei, e, r, c);
        if (r >= N_NODES || c >= N_NODES) return;
        float w = -g_dis[r] * ew[e] * g_dis[c];
        unsigned slot = (unsigned)atomicAdd(&g_cur[c], 1);
        if (slot >= N_EDGES) slot = N_EDGES - 1;
        g_pack[slot] = make_float2(__int_as_float((int)r), w);
    }
}
__global__ void __launch_bounds__(256)
prop_kernel(const float* __restrict__ x, int phase) {
    int gt = blockIdx.x * blockDim.x + threadIdx.x;
    int node = gt >> 5;
    int lane = gt & 31;
    if (node >= N_NODES) return;
    const float* src = (phase == 0) ? x : g_T1;
    float*       dst = (phase == 0) ? g_T1 : g_T2;
    int beg = g_off[node];
    int end = g_off[node + 1];
    if (beg < 0) beg = 0;
    if (end > N_EDGES) end = N_EDGES;
    const float2* s2 = reinterpret_cast<const float2*>(src);
    float ax = 0.f, ay = 0.f;
    int j = beg;
    for (; j + 2 <= end; j += 2) {
        float2 p0 = g_pack[j];
        float2 p1 = g_pack[j + 1];
        unsigned r0 = min((unsigned)__float_as_int(p0.x), N_NODES - 1u);
        unsigned r1 = min((unsigned)__float_as_int(p1.x), N_NODES - 1u);
        float2 v0 = s2[r0 * 32 + lane];
        float2 v1 = s2[r1 * 32 + lane];
        ax += p0.y * v0.x;  ay += p0.y * v0.y;
        ax += p1.y * v1.x;  ay += p1.y * v1.y;
    }
    if (j < end) {
        float2 p0 = g_pack[j];
        unsigned r0 = min((unsigned)__float_as_int(p0.x), N_NODES - 1u);
        float2 v0 = s2[r0 * 32 + lane];
        ax += p0.y * v0.x;  ay += p0.y * v0.y;
    }
    reinterpret_cast<float2*>(dst)[node * 32 + lane] = make_float2(ax, ay);
}

// WcT[320][192] (transposed combined weights) + bias[320]
__global__ void prep_weights_kernel(
    const float* __restrict__ W10, const float* __restrict__ b1,
    const float* __restrict__ W20, const float* __restrict__ W21, const float* __restrict__ b2,
    const float* __restrict__ W30, const float* __restrict__ W31, const float* __restrict__ W32,
    const float* __restrict__ b3)
{
    int i = blockIdx.x * blockDim.x + threadIdx.x;
    if (i >= WC_ROWS * WC_COLS) return;
    int k = i / WC_COLS;
    int c = i % WC_COLS;
    float v = 0.f;
    if (k < 64) {
        if (c < 100)       v = W10[k * 100 + c];
        else if (c < 200)  v = W20[k * 100 + (c - 100)];
        else if (c < 300)  v = W30[k * 100 + (c - 200)] - W32[k * 100 + (c - 200)];
    } else if (k < 128) {
        int kk = k - 64;
        if (c >= 100 && c < 200)      v = W21[kk * 100 + (c - 100)];
        else if (c >= 200 && c < 300) v = W31[kk * 100 + (c - 200)];
    } else {
        int kk = k - 128;
        if (c >= 200 && c < 300) v = 2.f * W32[kk * 100 + (c - 200)];
    }
    g_WcT[c * WC_ROWS + k] = v;
    if (i < WC_COLS) {
        float bv = 0.f;
        if (i < 100)      bv = b1[i];
        else if (i < 200) bv = b2[i - 100];
        else if (i < 300) bv = b3[i - 200];
        g_bias[i] = bv;
    }
}

// ---------------- bf16 mma.sync GEMM (3-MMA error-compensated split) ----------------
// out[100000,300] = [x|T1|T2p] @ Wc + bias.
// Block: 128 nodes x 64 cols, 8 warps (4 mrow x 2 ncol), warp tile 32x32.
// grid.y = col quarter (5 x 64); K chunks {1,2,2,3,3} of 64 (zero-block skipping).
// smem (bytes): Ahi[128][72]b16, Alo, Bhi[64][72]b16, Blo ; 144B row pitch -> ldmatrix conflict-free.
#define SA_HI 0
#define SA_LO 18432
#define SB_HI 36864
#define SB_LO 46080
#define SM_GEMM 55296

__device__ __forceinline__ uint32_t smem_u32(const void* p) {
    uint32_t a;
    asm("{ .reg .u64 t; cvta.to.shared.u64 t, %1; cvt.u32.u64 %0, t; }" : "=r"(a) : "l"(p));
    return a;
}
__device__ __forceinline__ void ldm_x4(uint32_t& r0, uint32_t& r1, uint32_t& r2, uint32_t& r3, uint32_t a) {
    asm volatile("ldmatrix.sync.aligned.m8n8.x4.shared.b16 {%0,%1,%2,%3}, [%4];"
        : "=r"(r0), "=r"(r1), "=r"(r2), "=r"(r3) : "r"(a));
}
__device__ __forceinline__ void mma_bf16(float* d, const uint32_t* a, uint32_t b0, uint32_t b1) {
    asm volatile("mma.sync.aligned.m16n8k16.row.col.f32.bf16.bf16.f32 "
        "{%0,%1,%2,%3}, {%4,%5,%6,%7}, {%8,%9}, {%0,%1,%2,%3};"
        : "+f"(d[0]), "+f"(d[1]), "+f"(d[2]), "+f"(d[3])
        : "r"(a[0]), "r"(a[1]), "r"(a[2]), "r"(a[3]), "r"(b0), "r"(b1));
}
__device__ __forceinline__ void split4(float4 v, uint2& hi, uint2& lo) {
    __nv_bfloat162 h01 = __floats2bfloat162_rn(v.x, v.y);
    __nv_bfloat162 h23 = __floats2bfloat162_rn(v.z, v.w);
    float lx = v.x - __bfloat162float(__low2bfloat16(h01));
    float ly = v.y - __bfloat162float(__high2bfloat16(h01));
    float lz = v.z - __bfloat162float(__low2bfloat16(h23));
    float lw = v.w - __bfloat162float(__high2bfloat16(h23));
    __nv_bfloat162 l01 = __floats2bfloat162_rn(lx, ly);
    __nv_bfloat162 l23 = __floats2bfloat162_rn(lz, lw);
    hi.x = *reinterpret_cast<uint32_t*>(&h01);
    hi.y = *reinterpret_cast<uint32_t*>(&h23);
    lo.x = *reinterpret_cast<uint32_t*>(&l01);
    lo.y = *reinterpret_cast<uint32_t*>(&l23);
}

__global__ void __launch_bounds__(256, 2)
gemm_kernel(const float* __restrict__ x, float* __restrict__ out)
{
    extern __shared__ __align__(16) char smem[];
    const uint32_t sb = smem_u32(smem);
    const int tid = threadIdx.x;
    const int wid = tid >> 5;
    const int lane = tid & 31;
    const int wr = wid & 3;          // warp row (32 nodes)
    const int wc = wid >> 2;         // warp col (32 cols)
    const int tile = blockIdx.x;     // 128-node tile
    const int q = blockIdx.y;        // 64-col quarter
    const int nch = (q == 0) ? 1 : (q < 3) ? 2 : 3;

    float acc[2][4][4];
#pragma unroll
    for (int mt = 0; mt < 2; mt++)
#pragma unroll
        for (int nt = 0; nt < 4; nt++)
#pragma unroll
            for (int i = 0; i < 4; i++) acc[mt][nt][i] = 0.f;

    // precomputed ldmatrix lane addresses (offsets within each split array)
    const uint32_t aRowOff = (uint32_t)((wr * 32 + (lane & 15)) * 144 + (lane >> 4) * 16);
    const uint32_t bRowBase = (uint32_t)((wc * 32 + ((lane >> 4) << 3) + (lane & 7)) * 144
                                         + (((lane >> 3) & 1) ? 16 : 0));

    for (int c = 0; c < nch; c++) {
        __syncthreads();
        // stage A: 128 rows x 64 k fp32 -> bf16 hi/lo
        const float4* s4 = (c == 0) ? reinterpret_cast<const float4*>(x)
                         : (c == 1) ? reinterpret_cast<const float4*>(g_T1)
                                    : reinterpret_cast<const float4*>(g_T2);
#pragma unroll
        for (int i = 0; i < 8; i++) {
            int idx = tid + i * 256;          // 0..2047
            int row = idx >> 4;               // 0..127
            int f4 = idx & 15;                // 0..15
            int node = tile * 128 + row;
            float4 v = make_float4(0.f, 0.f, 0.f, 0.f);
            if (node < N_NODES) v = s4[node * 16 + f4];
            uint2 hi, lo; split4(v, hi, lo);
            uint32_t off = (uint32_t)(row * 144 + f4 * 8);
            *reinterpret_cast<uint2*>(smem + SA_HI + off) = hi;
            *reinterpret_cast<uint2*>(smem + SA_LO + off) = lo;
        }
        // stage B: 64 cols x 64 k fp32 from WcT -> bf16 hi/lo
#pragma unroll
        for (int i = 0; i < 4; i++) {
            int idx = tid + i * 256;          // 0..1023
            int nrow = idx >> 4;              // 0..63
            int f4 = idx & 15;
            float4 v = *reinterpret_cast<const float4*>(
                &g_WcT[(q * 64 + nrow) * WC_ROWS + c * 64 + f4 * 4]);
            uint2 hi, lo; split4(v, hi, lo);
            uint32_t off = (uint32_t)(nrow * 144 + f4 * 8);
            *reinterpret_cast<uint2*>(smem + SB_HI + off) = hi;
            *reinterpret_cast<uint2*>(smem + SB_LO + off) = lo;
        }
        __syncthreads();

#pragma unroll
        for (int ks = 0; ks < 4; ks++) {
            uint32_t k0b = (uint32_t)(ks * 32);   // 16 k * 2B
            uint32_t ahi[2][4], alo[2][4];
#pragma unroll
            for (int mt = 0; mt < 2; mt++) {
                uint32_t aoff = aRowOff + (uint32_t)(mt * 16 * 144) + k0b;
                ldm_x4(ahi[mt][0], ahi[mt][1], ahi[mt][2], ahi[mt][3], sb + SA_HI + aoff);
                ldm_x4(alo[mt][0], alo[mt][1], alo[mt][2], alo[mt][3], sb + SA_LO + aoff);
            }
            uint32_t bhi[4][2], blo[4][2];
#pragma unroll
            for (int g2 = 0; g2 < 2; g2++) {      // each x4 covers 2 n-tiles
                uint32_t boff = bRowBase + (uint32_t)(g2 * 16 * 144) + k0b;
                ldm_x4(bhi[g2 * 2][0], bhi[g2 * 2][1], bhi[g2 * 2 + 1][0], bhi[g2 * 2 + 1][1],
                       sb + SB_HI + boff);
                ldm_x4(blo[g2 * 2][0], blo[g2 * 2][1], blo[g2 * 2 + 1][0], blo[g2 * 2 + 1][1],
                       sb + SB_LO + boff);
            }
#pragma unroll
            for (int mt = 0; mt < 2; mt++)
#pragma unroll
                for (int nt = 0; nt < 4; nt++) {
                    mma_bf16(acc[mt][nt], ahi[mt], bhi[nt][0], bhi[nt][1]);
                    mma_bf16(acc[mt][nt], ahi[mt], blo[nt][0], blo[nt][1]);
                    mma_bf16(acc[mt][nt], alo[mt], bhi[nt][0], bhi[nt][1]);
                }
        }
    }

    // epilogue: D frag thread t: rows g, g+8; cols 2*(t%4)+{0,1}
    const int g = lane >> 2;
    const int c2 = (lane & 3) * 2;
#pragma unroll
    for (int mt = 0; mt < 2; mt++)
#pragma unroll
        for (int nt = 0; nt < 4; nt++) {
            int col = q * 64 + wc * 32 + nt * 8 + c2;
            if (col >= OUT_COLS) continue;
            float2 bv = *reinterpret_cast<const float2*>(&g_bias[col]);
#pragma unroll
            for (int h = 0; h < 2; h++) {
                int node = tile * 128 + wr * 32 + mt * 16 + g + h * 8;
                if (node < N_NODES) {
                    float2 o = make_float2(acc[mt][nt][h * 2 + 0] + bv.x,
                                           acc[mt][nt][h * 2 + 1] + bv.y);
                    *reinterpret_cast<float2*>(&out[(long long)node * OUT_COLS + col]) = o;
                }
            }
        }
}

// ---------------- launch ----------------
extern "C" void kernel_launch(void* const* d_in, const int* in_sizes, int n_in,
                              void* d_out, int out_size)
{
    const float* x = nullptr;
    const void*  ei = nullptr;
    const float* ew = nullptr;
    const float* Ws[6] = {};
    const float* Bs[3] = {};
    int nw = 0, nb = 0;
    for (int i = 0; i < n_in; i++) {
        int s = in_sizes[i];
        if (s == N_NODES * D_IN)      x = (const float*)d_in[i];
        else if (s == 2 * N_EDGES)    ei = d_in[i];
        else if (s == N_EDGES)        ew = (const float*)d_in[i];
        else if (s == D_IN * 100)     { if (nw < 6) Ws[nw++] = (const float*)d_in[i]; }
        else if (s == 100)            { if (nb < 3) Bs[nb++] = (const float*)d_in[i]; }
    }
    if (!x)  x  = (const float*)d_in[0];
    if (!ei) ei = d_in[1];
    if (!ew) ew = (const float*)d_in[2];
    if (nw < 6) {
        Ws[0] = (const float*)d_in[3];  Ws[1] = (const float*)d_in[5];
        Ws[2] = (const float*)d_in[6];  Ws[3] = (const float*)d_in[8];
        Ws[4] = (const float*)d_in[9];  Ws[5] = (const float*)d_in[10];
    }
    if (nb < 3) {
        Bs[0] = (const float*)d_in[4];  Bs[1] = (const float*)d_in[7];
        Bs[2] = (const float*)d_in[11];
    }
    float* out = (float*)d_out;

    cudaFuncSetAttribute(gemm_kernel, cudaFuncAttributeMaxDynamicSharedMemorySize, SM_GEMM);

    const int B = 256;
    const int nodeGrid = (N_NODES + B - 1) / B;
    const int edgeGrid = (N_EDGES + B - 1) / B;

    detect_dtype_kernel<<<1, 256>>>((const int*)ei);
    zero_kernel<<<nodeGrid, B>>>();
    deg_hist_kernel<<<edgeGrid, B>>>(ei, ew);
    dis_kernel<<<nodeGrid, B>>>();
    scan1_kernel<<<SCAN_NB, SCAN_BS>>>();
    scan2_kernel<<<1, 128>>>();
    finalize_off_kernel<<<nodeGrid, B>>>();
    fill_kernel<<<edgeGrid, B>>>(ei, ew);

    {
        long long items = (long long)N_NODES * 32;
        int grid = (int)((items + B - 1) / B);
        prop_kernel<<<grid, B>>>(x, 0);
        prop_kernel<<<grid, B>>>(x, 1);
    }

    prep_weights_kernel<<<(WC_ROWS * WC_COLS + B - 1) / B, B>>>(
        Ws[0], Bs[0], Ws[1], Ws[2], Bs[1], Ws[3], Ws[4], Ws[5], Bs[2]);

    {
        dim3 grid((N_NODES + 127) / 128, 5);
        gemm_kernel<<<grid, 256, SM_GEMM>>>(x, out);
    }
}